// round 1
// baseline (speedup 1.0000x reference)
#include <cuda_runtime.h>
#include <cstdint>
#include <cstddef>

#define H_DIM 128
#define TILE_N 64
#define BK 32
#define MAX_E 1048576
#define MAX_NODES 100480
#define MAX_SIDE 51200
#define PSTRIDE 12
#define MAX_C 12

// ---------------- device scratch (no allocations allowed) ----------------
__device__ float g_x  [(size_t)MAX_NODES * H_DIM];
__device__ float g_hs [(size_t)MAX_NODES * H_DIM];
__device__ float g_acc[(size_t)MAX_NODES * H_DIM];
__device__ int   g_deg [MAX_NODES];
__device__ float g_dinv[MAX_NODES];
__device__ int   g_row[MAX_E];
__device__ int   g_col[MAX_E];
__device__ float g_pu[(size_t)MAX_SIDE * PSTRIDE];
__device__ float g_pm[(size_t)MAX_SIDE * PSTRIDE];
__device__ int   g_is64;

// ---------------- edge dtype detect + convert ----------------
// If the buffer is really int32 [2E], reading as int64 fuses pairs; since all
// valid ids < 50000, a genuine int64 buffer has every value in [0, 2^32).
__global__ void mp_detect_kernel(const void* ei)
{
    if (threadIdx.x == 0 && blockIdx.x == 0) {
        const long long* p = (const long long*)ei;
        int is64 = 1;
        #pragma unroll 1
        for (int i = 0; i < 32; i++) {
            long long v = p[i];
            if (v < 0 || v >= (1LL << 32)) { is64 = 0; break; }
        }
        g_is64 = is64;
    }
}

__global__ void mp_convert_kernel(const void* ei, int E)
{
    int e = blockIdx.x * blockDim.x + threadIdx.x;
    if (e >= E) return;
    if (g_is64) {
        const long long* p = (const long long*)ei;
        g_row[e] = (int)p[e];
        g_col[e] = (int)p[(size_t)E + e];
    } else {
        const int* p = (const int*)ei;
        g_row[e] = p[e];
        g_col[e] = p[E + e];
    }
}

// ---------------- degree / normalization ----------------
__global__ void mp_deg_init_kernel(int N)
{
    int i = blockIdx.x * blockDim.x + threadIdx.x;
    if (i < N) g_deg[i] = 1;   // self-loop
}

__global__ void mp_deg_count_kernel(int E)
{
    int e = blockIdx.x * blockDim.x + threadIdx.x;
    if (e < E) atomicAdd(&g_deg[g_col[e]], 1);
}

__global__ void mp_dinv_kernel(int N)
{
    int i = blockIdx.x * blockDim.x + threadIdx.x;
    if (i < N) g_dinv[i] = rsqrtf((float)g_deg[i]);
}

// ---------------- node linear: Y = (X @ W^T + b) [* dinv] ----------------
// Tile: 64 nodes x 128 outs per block, 256 threads, each thread 4x8 microtile.
// SCALE: multiply row by g_dinv[node].  DUAL: also write a second copy (acc
// initialized to hs == self-loop contribution).
template<int K, bool SCALE, bool DUAL>
__global__ void mp_linear_kernel(const float* __restrict__ X, int N,
                                 const float* __restrict__ W,
                                 const float* __restrict__ B,
                                 float* __restrict__ Y0,
                                 float* __restrict__ Y1)
{
    __shared__ __align__(16) float Ws[BK][H_DIM];   // transposed chunk [k][o]
    __shared__ float Xs[TILE_N][BK + 1];

    const int tid = threadIdx.x;
    const int tx = tid & 15;    // out-group (8 outs)
    const int ty = tid >> 4;    // node-group (4 nodes)
    const int node0 = blockIdx.x * TILE_N;

    float acc[4][8];
    #pragma unroll
    for (int i = 0; i < 4; i++)
        #pragma unroll
        for (int j = 0; j < 8; j++) acc[i][j] = 0.f;

    #pragma unroll 1
    for (int kc = 0; kc < K; kc += BK) {
        // W chunk: H_DIM x BK floats = 1024 float4, 4 per thread
        #pragma unroll
        for (int j = 0; j < (H_DIM * BK / 4) / 256; j++) {
            int f = tid + j * 256;
            int o = f >> 3;
            int q = f & 7;
            float4 v = *reinterpret_cast<const float4*>(W + (size_t)o * K + kc + q * 4);
            Ws[q * 4 + 0][o] = v.x;
            Ws[q * 4 + 1][o] = v.y;
            Ws[q * 4 + 2][o] = v.z;
            Ws[q * 4 + 3][o] = v.w;
        }
        // X tile: TILE_N x BK = 512 float4, 2 per thread
        #pragma unroll
        for (int j = 0; j < (TILE_N * BK / 4) / 256; j++) {
            int f = tid + j * 256;
            int n = f >> 3;
            int q = f & 7;
            int node = node0 + n;
            if (node >= N) node = N - 1;           // clamped (stores guarded)
            float4 v = *reinterpret_cast<const float4*>(X + (size_t)node * K + kc + q * 4);
            Xs[n][q * 4 + 0] = v.x;
            Xs[n][q * 4 + 1] = v.y;
            Xs[n][q * 4 + 2] = v.z;
            Xs[n][q * 4 + 3] = v.w;
        }
        __syncthreads();

        #pragma unroll 8
        for (int kk = 0; kk < BK; kk++) {
            const float4* wp = reinterpret_cast<const float4*>(&Ws[kk][0]);
            float4 w0 = wp[tx * 2 + 0];
            float4 w1 = wp[tx * 2 + 1];
            #pragma unroll
            for (int i = 0; i < 4; i++) {
                float xv = Xs[ty * 4 + i][kk];
                acc[i][0] += xv * w0.x; acc[i][1] += xv * w0.y;
                acc[i][2] += xv * w0.z; acc[i][3] += xv * w0.w;
                acc[i][4] += xv * w1.x; acc[i][5] += xv * w1.y;
                acc[i][6] += xv * w1.z; acc[i][7] += xv * w1.w;
            }
        }
        __syncthreads();
    }

    float breg[8];
    #pragma unroll
    for (int j = 0; j < 8; j++) breg[j] = B[tx * 8 + j];

    #pragma unroll
    for (int i = 0; i < 4; i++) {
        int node = node0 + ty * 4 + i;
        if (node >= N) continue;
        float s = SCALE ? g_dinv[node] : 1.f;
        float4 o0, o1;
        o0.x = (acc[i][0] + breg[0]) * s;
        o0.y = (acc[i][1] + breg[1]) * s;
        o0.z = (acc[i][2] + breg[2]) * s;
        o0.w = (acc[i][3] + breg[3]) * s;
        o1.x = (acc[i][4] + breg[4]) * s;
        o1.y = (acc[i][5] + breg[5]) * s;
        o1.z = (acc[i][6] + breg[6]) * s;
        o1.w = (acc[i][7] + breg[7]) * s;
        float* dst0 = Y0 + (size_t)node * H_DIM + tx * 8;
        *reinterpret_cast<float4*>(dst0)     = o0;
        *reinterpret_cast<float4*>(dst0 + 4) = o1;
        if (DUAL) {
            float* dst1 = Y1 + (size_t)node * H_DIM + tx * 8;
            *reinterpret_cast<float4*>(dst1)     = o0;
            *reinterpret_cast<float4*>(dst1 + 4) = o1;
        }
    }
}

// ---------------- scatter: acc[col] += hs[row], one warp per edge ----------------
__global__ void mp_scatter_kernel(int E)
{
    int id = blockIdx.x * blockDim.x + threadIdx.x;
    int e = id >> 5;
    if (e >= E) return;
    int lane = id & 31;
    int r = g_row[e];
    int c = g_col[e];
    float4 v = *reinterpret_cast<const float4*>(g_hs + (size_t)r * H_DIM + lane * 4);
    float* dst = g_acc + (size_t)c * H_DIM + lane * 4;
    atomicAdd(dst + 0, v.x);
    atomicAdd(dst + 1, v.y);
    atomicAdd(dst + 2, v.z);
    atomicAdd(dst + 3, v.w);
}

// ---------------- x = relu(dinv * acc) ----------------
__global__ void mp_finalize_kernel(int N)
{
    int i = blockIdx.x * blockDim.x + threadIdx.x;
    int total = N * (H_DIM / 4);
    if (i >= total) return;
    int n = i >> 5;                       // /(H_DIM/4)
    float s = g_dinv[n];
    float4 v = reinterpret_cast<const float4*>(g_acc)[i];
    v.x = fmaxf(v.x * s, 0.f);
    v.y = fmaxf(v.y * s, 0.f);
    v.z = fmaxf(v.z * s, 0.f);
    v.w = fmaxf(v.w * s, 0.f);
    reinterpret_cast<float4*>(g_x)[i] = v;
}

// ---------------- node projection to C dims: pu = xu@WeU^T + be, pm = xm@WeM^T ----------------
__global__ void mp_proj_kernel(const float* __restrict__ We,
                               const float* __restrict__ be,
                               int Nu, int Nm, int C)
{
    __shared__ float WeS[MAX_C][2 * H_DIM];
    __shared__ float beS[MAX_C];
    int tid = threadIdx.x;
    for (int i = tid; i < C * 2 * H_DIM; i += blockDim.x)
        WeS[i / (2 * H_DIM)][i % (2 * H_DIM)] = We[i];
    if (tid < C) beS[tid] = be[tid];
    __syncthreads();

    int n = blockIdx.x * blockDim.x + tid;
    if (n >= Nu + Nm) return;
    bool isU = n < Nu;
    const float4* src = reinterpret_cast<const float4*>(g_x + (size_t)n * H_DIM);
    int wo = isU ? 0 : H_DIM;

    float acc[MAX_C];
    #pragma unroll
    for (int c = 0; c < MAX_C; c++) acc[c] = (c < C && isU) ? beS[c] : 0.f;

    #pragma unroll 4
    for (int q = 0; q < H_DIM / 4; q++) {
        float4 v = src[q];
        int k = q * 4 + wo;
        #pragma unroll
        for (int c = 0; c < MAX_C; c++) {
            if (c < C) {
                acc[c] += v.x * WeS[c][k + 0] + v.y * WeS[c][k + 1]
                        + v.z * WeS[c][k + 2] + v.w * WeS[c][k + 3];
            }
        }
    }

    float* dst = isU ? (g_pu + (size_t)n * PSTRIDE)
                     : (g_pm + (size_t)(n - Nu) * PSTRIDE);
    for (int c = 0; c < C; c++) dst[c] = acc[c];
}

// ---------------- out[e] = pu[row[e]] + pm[col[e]] ----------------
__global__ void mp_edge_out_kernel(float* __restrict__ out, int E, int C)
{
    int e = blockIdx.x * blockDim.x + threadIdx.x;
    if (e >= E) return;
    int r = g_row[e];
    int c = g_col[e];
    const float* a = g_pu + (size_t)r * PSTRIDE;
    const float* b = g_pm + (size_t)c * PSTRIDE;
    float* o = out + (size_t)e * C;
    if ((C & 1) == 0) {
        for (int k = 0; k < C; k += 2) {
            float2 av = *reinterpret_cast<const float2*>(a + k);
            float2 bv = *reinterpret_cast<const float2*>(b + k);
            float2 ov;
            ov.x = av.x + bv.x;
            ov.y = av.y + bv.y;
            *reinterpret_cast<float2*>(o + k) = ov;
        }
    } else {
        for (int k = 0; k < C; k++) o[k] = a[k] + b[k];
    }
}

// ---------------- host launch ----------------
extern "C" void kernel_launch(void* const* d_in, const int* in_sizes, int n_in,
                              void* d_out, int out_size)
{
    const float* x_user  = (const float*)d_in[0];
    const float* x_movie = (const float*)d_in[1];
    const void*  eidx    = d_in[2];
    const float* Wu = (const float*)d_in[3];
    const float* bu = (const float*)d_in[4];
    const float* Wm = (const float*)d_in[5];
    const float* bm = (const float*)d_in[6];
    const float* W1 = (const float*)d_in[7];
    const float* b1 = (const float*)d_in[8];
    const float* W2 = (const float*)d_in[9];
    const float* b2 = (const float*)d_in[10];
    const float* We = (const float*)d_in[11];
    const float* be = (const float*)d_in[12];
    float* out = (float*)d_out;

    const int H  = in_sizes[4];
    const int Fu = in_sizes[3] / H;
    const int Fm = in_sizes[5] / H;
    const int Nu = in_sizes[0] / Fu;
    const int Nm = in_sizes[1] / Fm;
    int E        = in_sizes[2] / 2;
    const int C  = in_sizes[12];
    const int Ntot = Nu + Nm;
    if (E > MAX_E) E = MAX_E;

    float* xp;   cudaGetSymbolAddress((void**)&xp,   g_x);
    float* hsp;  cudaGetSymbolAddress((void**)&hsp,  g_hs);
    float* accp; cudaGetSymbolAddress((void**)&accp, g_acc);

    mp_detect_kernel<<<1, 32>>>(eidx);
    mp_convert_kernel<<<(E + 255) / 256, 256>>>(eidx, E);
    mp_deg_init_kernel<<<(Ntot + 255) / 256, 256>>>(Ntot);
    mp_deg_count_kernel<<<(E + 255) / 256, 256>>>(E);
    mp_dinv_kernel<<<(Ntot + 255) / 256, 256>>>(Ntot);

    // Input feature transforms into g_x
    {
        int g = (Nu + TILE_N - 1) / TILE_N;
        if (Fu == 32)       mp_linear_kernel< 32, false, false><<<g, 256>>>(x_user, Nu, Wu, bu, xp, nullptr);
        else if (Fu == 64)  mp_linear_kernel< 64, false, false><<<g, 256>>>(x_user, Nu, Wu, bu, xp, nullptr);
        else                mp_linear_kernel<128, false, false><<<g, 256>>>(x_user, Nu, Wu, bu, xp, nullptr);
    }
    {
        int g = (Nm + TILE_N - 1) / TILE_N;
        float* dst = xp + (size_t)Nu * H_DIM;
        if (Fm == 32)       mp_linear_kernel< 32, false, false><<<g, 256>>>(x_movie, Nm, Wm, bm, dst, nullptr);
        else if (Fm == 64)  mp_linear_kernel< 64, false, false><<<g, 256>>>(x_movie, Nm, Wm, bm, dst, nullptr);
        else                mp_linear_kernel<128, false, false><<<g, 256>>>(x_movie, Nm, Wm, bm, dst, nullptr);
    }

    int gN = (Ntot + TILE_N - 1) / TILE_N;
    int gS = (int)(((long long)E * 32 + 255) / 256);
    int gF = (Ntot * (H_DIM / 4) + 255) / 256;

    // GNN layer 1
    mp_linear_kernel<128, true, true><<<gN, 256>>>(xp, Ntot, W1, b1, hsp, accp);
    mp_scatter_kernel<<<gS, 256>>>(E);
    mp_finalize_kernel<<<gF, 256>>>(Ntot);

    // GNN layer 2
    mp_linear_kernel<128, true, true><<<gN, 256>>>(xp, Ntot, W2, b2, hsp, accp);
    mp_scatter_kernel<<<gS, 256>>>(E);
    mp_finalize_kernel<<<gF, 256>>>(Ntot);

    // Edge head: project nodes to C dims, then gather+add per edge
    mp_proj_kernel<<<(Ntot + 255) / 256, 256>>>(We, be, Nu, Nm, C);
    mp_edge_out_kernel<<<(E + 255) / 256, 256>>>(out, E, C);
}

// round 2
// speedup vs baseline: 1.3058x; 1.3058x over previous
#include <cuda_runtime.h>
#include <cstdint>
#include <cstddef>

#define H_DIM 128
#define TILE_N 64
#define BK 32
#define MAX_E 1048576
#define MAX_NODES 100480
#define MAX_SIDE 51200
#define PSTRIDE 12
#define MAX_C 12

// ---------------- device scratch (no allocations allowed) ----------------
__device__ __align__(16) float g_x  [(size_t)MAX_NODES * H_DIM];
__device__ __align__(16) float g_hs [(size_t)MAX_NODES * H_DIM];
__device__ __align__(16) float g_acc[(size_t)MAX_NODES * H_DIM];
__device__ int   g_deg [MAX_NODES];
__device__ float g_dinv[MAX_NODES];
__device__ int   g_row[MAX_E];
__device__ int   g_col[MAX_E];
__device__ float g_pu[(size_t)MAX_SIDE * PSTRIDE];
__device__ float g_pm[(size_t)MAX_SIDE * PSTRIDE];
__device__ int   g_is64;

// packed f32x2 FMA: d = a*b + d  (FFMA2 — only reachable via explicit PTX)
__device__ __forceinline__ void ffma2(unsigned long long& d,
                                      unsigned long long a,
                                      unsigned long long b)
{
    asm("fma.rn.f32x2 %0, %1, %2, %3;" : "=l"(d) : "l"(a), "l"(b), "l"(d));
}

// ---------------- edge dtype detect ----------------
// If the buffer is really int32 [2E], reading as int64 fuses pairs; since all
// valid ids < 50000, a genuine int64 buffer has every value in [0, 2^32).
__global__ void mp_detect_kernel(const void* ei)
{
    if (threadIdx.x == 0 && blockIdx.x == 0) {
        const long long* p = (const long long*)ei;
        int is64 = 1;
        #pragma unroll 1
        for (int i = 0; i < 32; i++) {
            long long v = p[i];
            if (v < 0 || v >= (1LL << 32)) { is64 = 0; break; }
        }
        g_is64 = is64;
    }
}

// ---------------- convert edges to int32 + count in-degree (fused) ----------------
__global__ void mp_convert_kernel(const void* ei, int E)
{
    int e = blockIdx.x * blockDim.x + threadIdx.x;
    if (e >= E) return;
    int r, c;
    if (g_is64) {
        const long long* p = (const long long*)ei;
        r = (int)p[e];
        c = (int)p[(size_t)E + e];
    } else {
        const int* p = (const int*)ei;
        r = p[e];
        c = p[E + e];
    }
    g_row[e] = r;
    g_col[e] = c;
    atomicAdd(&g_deg[c], 1);
}

__global__ void mp_deg_init_kernel(int N)
{
    int i = blockIdx.x * blockDim.x + threadIdx.x;
    if (i < N) g_deg[i] = 1;   // self-loop
}

__global__ void mp_dinv_kernel(int N)
{
    int i = blockIdx.x * blockDim.x + threadIdx.x;
    if (i < N) g_dinv[i] = rsqrtf((float)g_deg[i]);
}

// ---------------- node linear: Y = (X @ W^T + b) [* dinv] ----------------
// Tile: 64 nodes x 128 outs per block, 256 threads, each thread 4x8 microtile.
// Inner loop uses packed f32x2 FMA (adjacent output channels paired).
// SCALE: multiply row by g_dinv[node].  DUAL: also write a second copy (acc
// initialized to hs == self-loop contribution).
template<int K, bool SCALE, bool DUAL>
__global__ void mp_linear_kernel(const float* __restrict__ X, int N,
                                 const float* __restrict__ W,
                                 const float* __restrict__ B,
                                 float* __restrict__ Y0,
                                 float* __restrict__ Y1)
{
    __shared__ __align__(16) float  Ws[BK][H_DIM];      // transposed chunk [k][o]
    __shared__ __align__(16) float2 Xs[TILE_N][BK + 1]; // duplicated (v,v) pairs

    const int tid = threadIdx.x;
    const int tx = tid & 15;    // out-group (8 outs = 4 f32x2 pairs)
    const int ty = tid >> 4;    // node-group (4 nodes)
    const int node0 = blockIdx.x * TILE_N;

    unsigned long long acc[4][4];
    #pragma unroll
    for (int i = 0; i < 4; i++)
        #pragma unroll
        for (int j = 0; j < 4; j++) acc[i][j] = 0ull;

    #pragma unroll 1
    for (int kc = 0; kc < K; kc += BK) {
        // W chunk: H_DIM x BK floats = 1024 float4, 4 per thread
        #pragma unroll
        for (int j = 0; j < (H_DIM * BK / 4) / 256; j++) {
            int f = tid + j * 256;
            int o = f >> 3;
            int q = f & 7;
            float4 v = *reinterpret_cast<const float4*>(W + (size_t)o * K + kc + q * 4);
            Ws[q * 4 + 0][o] = v.x;
            Ws[q * 4 + 1][o] = v.y;
            Ws[q * 4 + 2][o] = v.z;
            Ws[q * 4 + 3][o] = v.w;
        }
        // X tile: TILE_N x BK = 512 float4, 2 per thread; store duplicated pairs
        #pragma unroll
        for (int j = 0; j < (TILE_N * BK / 4) / 256; j++) {
            int f = tid + j * 256;
            int n = f >> 3;
            int q = f & 7;
            int node = node0 + n;
            if (node >= N) node = N - 1;           // clamped (stores guarded)
            float4 v = *reinterpret_cast<const float4*>(X + (size_t)node * K + kc + q * 4);
            Xs[n][q * 4 + 0] = make_float2(v.x, v.x);
            Xs[n][q * 4 + 1] = make_float2(v.y, v.y);
            Xs[n][q * 4 + 2] = make_float2(v.z, v.z);
            Xs[n][q * 4 + 3] = make_float2(v.w, v.w);
        }
        __syncthreads();

        #pragma unroll 8
        for (int kk = 0; kk < BK; kk++) {
            const unsigned long long* wp =
                reinterpret_cast<const unsigned long long*>(&Ws[kk][0]);
            unsigned long long w0 = wp[tx * 4 + 0];
            unsigned long long w1 = wp[tx * 4 + 1];
            unsigned long long w2 = wp[tx * 4 + 2];
            unsigned long long w3 = wp[tx * 4 + 3];
            #pragma unroll
            for (int i = 0; i < 4; i++) {
                unsigned long long xv =
                    *reinterpret_cast<const unsigned long long*>(&Xs[ty * 4 + i][kk]);
                ffma2(acc[i][0], xv, w0);
                ffma2(acc[i][1], xv, w1);
                ffma2(acc[i][2], xv, w2);
                ffma2(acc[i][3], xv, w3);
            }
        }
        __syncthreads();
    }

    float breg[8];
    #pragma unroll
    for (int j = 0; j < 8; j++) breg[j] = B[tx * 8 + j];

    #pragma unroll
    for (int i = 0; i < 4; i++) {
        int node = node0 + ty * 4 + i;
        if (node >= N) continue;
        float s = SCALE ? g_dinv[node] : 1.f;
        float r[8];
        #pragma unroll
        for (int j = 0; j < 4; j++) {
            float2 p = *reinterpret_cast<float2*>(&acc[i][j]);
            r[2 * j + 0] = (p.x + breg[2 * j + 0]) * s;
            r[2 * j + 1] = (p.y + breg[2 * j + 1]) * s;
        }
        float4 o0 = make_float4(r[0], r[1], r[2], r[3]);
        float4 o1 = make_float4(r[4], r[5], r[6], r[7]);
        float* dst0 = Y0 + (size_t)node * H_DIM + tx * 8;
        *reinterpret_cast<float4*>(dst0)     = o0;
        *reinterpret_cast<float4*>(dst0 + 4) = o1;
        if (DUAL) {
            float* dst1 = Y1 + (size_t)node * H_DIM + tx * 8;
            *reinterpret_cast<float4*>(dst1)     = o0;
            *reinterpret_cast<float4*>(dst1 + 4) = o1;
        }
    }
}

// ---------------- scatter: acc[col] += hs[row], one warp per edge ----------------
// One red.global.add.v4.f32 per lane (16B), vs 4 scalar atomics before.
__global__ void mp_scatter_kernel(int E)
{
    int id = blockIdx.x * blockDim.x + threadIdx.x;
    int e = id >> 5;
    if (e >= E) return;
    int lane = id & 31;
    int r = g_row[e];
    int c = g_col[e];
    float4 v = *reinterpret_cast<const float4*>(g_hs + (size_t)r * H_DIM + lane * 4);
    float* dst = g_acc + (size_t)c * H_DIM + lane * 4;
    asm volatile("red.global.add.v4.f32 [%0], {%1, %2, %3, %4};"
                 :: "l"(dst), "f"(v.x), "f"(v.y), "f"(v.z), "f"(v.w)
                 : "memory");
}

// ---------------- x = relu(dinv * acc) ----------------
__global__ void mp_finalize_kernel(int N)
{
    int i = blockIdx.x * blockDim.x + threadIdx.x;
    int total = N * (H_DIM / 4);
    if (i >= total) return;
    int n = i >> 5;                       // /(H_DIM/4)
    float s = g_dinv[n];
    float4 v = reinterpret_cast<const float4*>(g_acc)[i];
    v.x = fmaxf(v.x * s, 0.f);
    v.y = fmaxf(v.y * s, 0.f);
    v.z = fmaxf(v.z * s, 0.f);
    v.w = fmaxf(v.w * s, 0.f);
    reinterpret_cast<float4*>(g_x)[i] = v;
}

// ---------------- node projection to C dims: pu = xu@WeU^T + be, pm = xm@WeM^T ----------------
__global__ void mp_proj_kernel(const float* __restrict__ We,
                               const float* __restrict__ be,
                               int Nu, int Nm, int C)
{
    __shared__ float WeS[MAX_C][2 * H_DIM];
    __shared__ float beS[MAX_C];
    int tid = threadIdx.x;
    for (int i = tid; i < C * 2 * H_DIM; i += blockDim.x)
        WeS[i / (2 * H_DIM)][i % (2 * H_DIM)] = We[i];
    if (tid < C) beS[tid] = be[tid];
    __syncthreads();

    int n = blockIdx.x * blockDim.x + tid;
    if (n >= Nu + Nm) return;
    bool isU = n < Nu;
    const float4* src = reinterpret_cast<const float4*>(g_x + (size_t)n * H_DIM);
    int wo = isU ? 0 : H_DIM;

    float acc[MAX_C];
    #pragma unroll
    for (int c = 0; c < MAX_C; c++) acc[c] = (c < C && isU) ? beS[c] : 0.f;

    #pragma unroll 4
    for (int q = 0; q < H_DIM / 4; q++) {
        float4 v = src[q];
        int k = q * 4 + wo;
        #pragma unroll
        for (int c = 0; c < MAX_C; c++) {
            if (c < C) {
                acc[c] += v.x * WeS[c][k + 0] + v.y * WeS[c][k + 1]
                        + v.z * WeS[c][k + 2] + v.w * WeS[c][k + 3];
            }
        }
    }

    float* dst = isU ? (g_pu + (size_t)n * PSTRIDE)
                     : (g_pm + (size_t)(n - Nu) * PSTRIDE);
    for (int c = 0; c < C; c++) dst[c] = acc[c];
}

// ---------------- out[e] = pu[row[e]] + pm[col[e]] ----------------
__global__ void mp_edge_out_kernel(float* __restrict__ out, int E, int C)
{
    int e = blockIdx.x * blockDim.x + threadIdx.x;
    if (e >= E) return;
    int r = g_row[e];
    int c = g_col[e];
    const float* a = g_pu + (size_t)r * PSTRIDE;
    const float* b = g_pm + (size_t)c * PSTRIDE;
    float* o = out + (size_t)e * C;
    if ((C & 1) == 0) {
        for (int k = 0; k < C; k += 2) {
            float2 av = *reinterpret_cast<const float2*>(a + k);
            float2 bv = *reinterpret_cast<const float2*>(b + k);
            float2 ov;
            ov.x = av.x + bv.x;
            ov.y = av.y + bv.y;
            *reinterpret_cast<float2*>(o + k) = ov;
        }
    } else {
        for (int k = 0; k < C; k++) o[k] = a[k] + b[k];
    }
}

// ---------------- host launch ----------------
extern "C" void kernel_launch(void* const* d_in, const int* in_sizes, int n_in,
                              void* d_out, int out_size)
{
    const float* x_user  = (const float*)d_in[0];
    const float* x_movie = (const float*)d_in[1];
    const void*  eidx    = d_in[2];
    const float* Wu = (const float*)d_in[3];
    const float* bu = (const float*)d_in[4];
    const float* Wm = (const float*)d_in[5];
    const float* bm = (const float*)d_in[6];
    const float* W1 = (const float*)d_in[7];
    const float* b1 = (const float*)d_in[8];
    const float* W2 = (const float*)d_in[9];
    const float* b2 = (const float*)d_in[10];
    const float* We = (const float*)d_in[11];
    const float* be = (const float*)d_in[12];
    float* out = (float*)d_out;

    const int H  = in_sizes[4];
    const int Fu = in_sizes[3] / H;
    const int Fm = in_sizes[5] / H;
    const int Nu = in_sizes[0] / Fu;
    const int Nm = in_sizes[1] / Fm;
    int E        = in_sizes[2] / 2;
    const int C  = in_sizes[12];
    const int Ntot = Nu + Nm;
    if (E > MAX_E) E = MAX_E;

    float* xp;   cudaGetSymbolAddress((void**)&xp,   g_x);
    float* hsp;  cudaGetSymbolAddress((void**)&hsp,  g_hs);
    float* accp; cudaGetSymbolAddress((void**)&accp, g_acc);

    mp_detect_kernel<<<1, 32>>>(eidx);
    mp_deg_init_kernel<<<(Ntot + 255) / 256, 256>>>(Ntot);
    mp_convert_kernel<<<(E + 255) / 256, 256>>>(eidx, E);
    mp_dinv_kernel<<<(Ntot + 255) / 256, 256>>>(Ntot);

    // Input feature transforms into g_x
    {
        int g = (Nu + TILE_N - 1) / TILE_N;
        if (Fu == 32)       mp_linear_kernel< 32, false, false><<<g, 256>>>(x_user, Nu, Wu, bu, xp, nullptr);
        else if (Fu == 64)  mp_linear_kernel< 64, false, false><<<g, 256>>>(x_user, Nu, Wu, bu, xp, nullptr);
        else                mp_linear_kernel<128, false, false><<<g, 256>>>(x_user, Nu, Wu, bu, xp, nullptr);
    }
    {
        int g = (Nm + TILE_N - 1) / TILE_N;
        float* dst = xp + (size_t)Nu * H_DIM;
        if (Fm == 32)       mp_linear_kernel< 32, false, false><<<g, 256>>>(x_movie, Nm, Wm, bm, dst, nullptr);
        else if (Fm == 64)  mp_linear_kernel< 64, false, false><<<g, 256>>>(x_movie, Nm, Wm, bm, dst, nullptr);
        else                mp_linear_kernel<128, false, false><<<g, 256>>>(x_movie, Nm, Wm, bm, dst, nullptr);
    }

    int gN = (Ntot + TILE_N - 1) / TILE_N;
    int gS = (int)(((long long)E * 32 + 255) / 256);
    int gF = (Ntot * (H_DIM / 4) + 255) / 256;

    // GNN layer 1
    mp_linear_kernel<128, true, true><<<gN, 256>>>(xp, Ntot, W1, b1, hsp, accp);
    mp_scatter_kernel<<<gS, 256>>>(E);
    mp_finalize_kernel<<<gF, 256>>>(Ntot);

    // GNN layer 2
    mp_linear_kernel<128, true, true><<<gN, 256>>>(xp, Ntot, W2, b2, hsp, accp);
    mp_scatter_kernel<<<gS, 256>>>(E);
    mp_finalize_kernel<<<gF, 256>>>(Ntot);

    // Edge head: project nodes to C dims, then gather+add per edge
    mp_proj_kernel<<<(Ntot + 255) / 256, 256>>>(We, be, Nu, Nm, C);
    mp_edge_out_kernel<<<(E + 255) / 256, 256>>>(out, E, C);
}

// round 3
// speedup vs baseline: 1.7639x; 1.3508x over previous
#include <cuda_runtime.h>
#include <cstdint>
#include <cstddef>

#define H_DIM 128
#define TILE_N 64
#define BK 32
#define MAX_E 1048576
#define MAX_NODES 100480
#define MAX_SIDE 51200
#define PSTRIDE 12
#define MAX_C 12
#define SCAN_B 256
#define MAX_SCAN_BLK 512

// ---------------- device scratch (no allocations allowed) ----------------
__device__ __align__(16) float g_x  [(size_t)MAX_NODES * H_DIM];
__device__ __align__(16) float g_hs [(size_t)MAX_NODES * H_DIM];
__device__ int   g_deg   [MAX_NODES];
__device__ int   g_off   [MAX_NODES];
__device__ int   g_cursor[MAX_NODES];
__device__ float g_dinv  [MAX_NODES];
__device__ int   g_row[MAX_E];
__device__ int   g_col[MAX_E];
__device__ int   g_csr[MAX_E];            // source node per bucketed edge
__device__ int   g_bsum [MAX_SCAN_BLK];
__device__ int   g_bsum2[MAX_SCAN_BLK];
__device__ float g_pu[(size_t)MAX_SIDE * PSTRIDE];
__device__ float g_pm[(size_t)MAX_SIDE * PSTRIDE];
__device__ int   g_is64;

// packed f32x2 FMA: d = a*b + d  (FFMA2 — only reachable via explicit PTX)
__device__ __forceinline__ void ffma2(unsigned long long& d,
                                      unsigned long long a,
                                      unsigned long long b)
{
    asm("fma.rn.f32x2 %0, %1, %2, %3;" : "=l"(d) : "l"(a), "l"(b), "l"(d));
}

// ---------------- edge dtype detect ----------------
// If the buffer is really int32 [2E], reading as int64 fuses pairs; since all
// valid ids < 50000, a genuine int64 buffer has every value in [0, 2^32).
__global__ void mp_detect_kernel(const void* ei)
{
    if (threadIdx.x == 0 && blockIdx.x == 0) {
        const long long* p = (const long long*)ei;
        int is64 = 1;
        #pragma unroll 1
        for (int i = 0; i < 32; i++) {
            long long v = p[i];
            if (v < 0 || v >= (1LL << 32)) { is64 = 0; break; }
        }
        g_is64 = is64;
    }
}

__global__ void mp_deg_zero_kernel(int N)
{
    int i = blockIdx.x * blockDim.x + threadIdx.x;
    if (i < N) g_deg[i] = 0;
}

// ---------------- convert edges to int32 + count in-degree (fused) ----------------
__global__ void mp_convert_kernel(const void* ei, int E)
{
    int e = blockIdx.x * blockDim.x + threadIdx.x;
    if (e >= E) return;
    int r, c;
    if (g_is64) {
        const long long* p = (const long long*)ei;
        r = (int)p[e];
        c = (int)p[(size_t)E + e];
    } else {
        const int* p = (const int*)ei;
        r = p[e];
        c = p[E + e];
    }
    g_row[e] = r;
    g_col[e] = c;
    atomicAdd(&g_deg[c], 1);
}

// ---------------- 3-phase exclusive scan over g_deg -> g_off ----------------
__global__ void mp_scan1_kernel(int N)
{
    __shared__ int sh[SCAN_B];
    int t = threadIdx.x;
    int i = blockIdx.x * SCAN_B + t;
    int v = (i < N) ? g_deg[i] : 0;
    sh[t] = v;
    __syncthreads();
    #pragma unroll
    for (int ofs = 1; ofs < SCAN_B; ofs <<= 1) {
        int u = (t >= ofs) ? sh[t - ofs] : 0;
        __syncthreads();
        sh[t] += u;
        __syncthreads();
    }
    if (i < N) g_off[i] = sh[t] - v;                 // exclusive within block
    if (t == SCAN_B - 1) g_bsum[blockIdx.x] = sh[t]; // block total
}

__global__ void mp_scan2_kernel(int nb)
{
    __shared__ int sh[MAX_SCAN_BLK];
    int t = threadIdx.x;
    int v = (t < nb) ? g_bsum[t] : 0;
    sh[t] = v;
    __syncthreads();
    #pragma unroll
    for (int ofs = 1; ofs < MAX_SCAN_BLK; ofs <<= 1) {
        int u = (t >= ofs) ? sh[t - ofs] : 0;
        __syncthreads();
        sh[t] += u;
        __syncthreads();
    }
    if (t < nb) g_bsum2[t] = sh[t] - v;              // exclusive block offsets
}

// add block offsets, init cursors, compute dinv (deg + self-loop)
__global__ void mp_scan3_kernel(int N)
{
    int i = blockIdx.x * blockDim.x + threadIdx.x;
    if (i >= N) return;
    int off = g_off[i] + g_bsum2[i >> 8];            // SCAN_B == 256
    g_off[i] = off;
    g_cursor[i] = off;
    g_dinv[i] = rsqrtf((float)(g_deg[i] + 1));
}

// ---------------- bucket fill: csr[pos] = row, bucketed by col ----------------
__global__ void mp_fill_kernel(int E)
{
    int e = blockIdx.x * blockDim.x + threadIdx.x;
    if (e >= E) return;
    int pos = atomicAdd(&g_cursor[g_col[e]], 1);
    g_csr[pos] = g_row[e];
}

// ---------------- node linear: Y = (X @ W^T + b) [* dinv] ----------------
// Tile: 64 nodes x 128 outs per block, 256 threads, each thread 4x8 microtile.
// Inner loop uses packed f32x2 FMA (adjacent output channels paired).
template<int K, bool SCALE>
__global__ void mp_linear_kernel(const float* __restrict__ X, int N,
                                 const float* __restrict__ W,
                                 const float* __restrict__ B,
                                 float* __restrict__ Y0)
{
    __shared__ __align__(16) float  Ws[BK][H_DIM];      // transposed chunk [k][o]
    __shared__ __align__(16) float2 Xs[TILE_N][BK + 1]; // duplicated (v,v) pairs

    const int tid = threadIdx.x;
    const int tx = tid & 15;    // out-group (8 outs = 4 f32x2 pairs)
    const int ty = tid >> 4;    // node-group (4 nodes)
    const int node0 = blockIdx.x * TILE_N;

    unsigned long long acc[4][4];
    #pragma unroll
    for (int i = 0; i < 4; i++)
        #pragma unroll
        for (int j = 0; j < 4; j++) acc[i][j] = 0ull;

    #pragma unroll 1
    for (int kc = 0; kc < K; kc += BK) {
        // W chunk: H_DIM x BK floats = 1024 float4, 4 per thread
        #pragma unroll
        for (int j = 0; j < (H_DIM * BK / 4) / 256; j++) {
            int f = tid + j * 256;
            int o = f >> 3;
            int q = f & 7;
            float4 v = *reinterpret_cast<const float4*>(W + (size_t)o * K + kc + q * 4);
            Ws[q * 4 + 0][o] = v.x;
            Ws[q * 4 + 1][o] = v.y;
            Ws[q * 4 + 2][o] = v.z;
            Ws[q * 4 + 3][o] = v.w;
        }
        // X tile: TILE_N x BK = 512 float4, 2 per thread; store duplicated pairs
        #pragma unroll
        for (int j = 0; j < (TILE_N * BK / 4) / 256; j++) {
            int f = tid + j * 256;
            int n = f >> 3;
            int q = f & 7;
            int node = node0 + n;
            if (node >= N) node = N - 1;           // clamped (stores guarded)
            float4 v = *reinterpret_cast<const float4*>(X + (size_t)node * K + kc + q * 4);
            Xs[n][q * 4 + 0] = make_float2(v.x, v.x);
            Xs[n][q * 4 + 1] = make_float2(v.y, v.y);
            Xs[n][q * 4 + 2] = make_float2(v.z, v.z);
            Xs[n][q * 4 + 3] = make_float2(v.w, v.w);
        }
        __syncthreads();

        #pragma unroll 8
        for (int kk = 0; kk < BK; kk++) {
            const unsigned long long* wp =
                reinterpret_cast<const unsigned long long*>(&Ws[kk][0]);
            unsigned long long w0 = wp[tx * 4 + 0];
            unsigned long long w1 = wp[tx * 4 + 1];
            unsigned long long w2 = wp[tx * 4 + 2];
            unsigned long long w3 = wp[tx * 4 + 3];
            #pragma unroll
            for (int i = 0; i < 4; i++) {
                unsigned long long xv =
                    *reinterpret_cast<const unsigned long long*>(&Xs[ty * 4 + i][kk]);
                ffma2(acc[i][0], xv, w0);
                ffma2(acc[i][1], xv, w1);
                ffma2(acc[i][2], xv, w2);
                ffma2(acc[i][3], xv, w3);
            }
        }
        __syncthreads();
    }

    float breg[8];
    #pragma unroll
    for (int j = 0; j < 8; j++) breg[j] = B[tx * 8 + j];

    #pragma unroll
    for (int i = 0; i < 4; i++) {
        int node = node0 + ty * 4 + i;
        if (node >= N) continue;
        float s = SCALE ? g_dinv[node] : 1.f;
        float r[8];
        #pragma unroll
        for (int j = 0; j < 4; j++) {
            float2 p = *reinterpret_cast<float2*>(&acc[i][j]);
            r[2 * j + 0] = (p.x + breg[2 * j + 0]) * s;
            r[2 * j + 1] = (p.y + breg[2 * j + 1]) * s;
        }
        float* dst0 = Y0 + (size_t)node * H_DIM + tx * 8;
        *reinterpret_cast<float4*>(dst0)     = make_float4(r[0], r[1], r[2], r[3]);
        *reinterpret_cast<float4*>(dst0 + 4) = make_float4(r[4], r[5], r[6], r[7]);
    }
}

// ---------------- aggregate: x[n] = relu(dinv[n]*(hs[n] + sum_nbr hs[src])) ----------------
// One warp per destination node. Neighbor ids loaded cooperatively (one LDG
// per lane, shfl-broadcast) so the 512B row gathers overlap (MLP ~ degree).
__global__ void mp_aggregate_kernel(int N)
{
    int id = blockIdx.x * blockDim.x + threadIdx.x;
    int n = id >> 5;
    if (n >= N) return;
    int lane = id & 31;

    const float4* hsp = reinterpret_cast<const float4*>(g_hs);
    float4 acc = __ldg(hsp + (size_t)n * (H_DIM / 4) + lane);   // self-loop

    int beg = g_off[n];
    int end = beg + g_deg[n];
    for (int base = beg; base < end; base += 32) {
        int m = end - base;
        if (m > 32) m = 32;
        int idx = (lane < m) ? g_csr[base + lane] : 0;
        #pragma unroll 4
        for (int j = 0; j < m; j++) {
            int r = __shfl_sync(0xffffffffu, idx, j);
            float4 v = __ldg(hsp + (size_t)r * (H_DIM / 4) + lane);
            acc.x += v.x; acc.y += v.y; acc.z += v.z; acc.w += v.w;
        }
    }

    float s = g_dinv[n];
    acc.x = fmaxf(acc.x * s, 0.f);
    acc.y = fmaxf(acc.y * s, 0.f);
    acc.z = fmaxf(acc.z * s, 0.f);
    acc.w = fmaxf(acc.w * s, 0.f);
    reinterpret_cast<float4*>(g_x)[(size_t)n * (H_DIM / 4) + lane] = acc;
}

// ---------------- node projection to C dims: pu = xu@WeU^T + be, pm = xm@WeM^T ----------------
__global__ void mp_proj_kernel(const float* __restrict__ We,
                               const float* __restrict__ be,
                               int Nu, int Nm, int C)
{
    __shared__ float WeS[MAX_C][2 * H_DIM];
    __shared__ float beS[MAX_C];
    int tid = threadIdx.x;
    for (int i = tid; i < C * 2 * H_DIM; i += blockDim.x)
        WeS[i / (2 * H_DIM)][i % (2 * H_DIM)] = We[i];
    if (tid < C) beS[tid] = be[tid];
    __syncthreads();

    int n = blockIdx.x * blockDim.x + tid;
    if (n >= Nu + Nm) return;
    bool isU = n < Nu;
    const float4* src = reinterpret_cast<const float4*>(g_x + (size_t)n * H_DIM);
    int wo = isU ? 0 : H_DIM;

    float acc[MAX_C];
    #pragma unroll
    for (int c = 0; c < MAX_C; c++) acc[c] = (c < C && isU) ? beS[c] : 0.f;

    #pragma unroll 4
    for (int q = 0; q < H_DIM / 4; q++) {
        float4 v = src[q];
        int k = q * 4 + wo;
        #pragma unroll
        for (int c = 0; c < MAX_C; c++) {
            if (c < C) {
                acc[c] += v.x * WeS[c][k + 0] + v.y * WeS[c][k + 1]
                        + v.z * WeS[c][k + 2] + v.w * WeS[c][k + 3];
            }
        }
    }

    float* dst = isU ? (g_pu + (size_t)n * PSTRIDE)
                     : (g_pm + (size_t)(n - Nu) * PSTRIDE);
    for (int c = 0; c < C; c++) dst[c] = acc[c];
}

// ---------------- out[e] = pu[row[e]] + pm[col[e]] ----------------
__global__ void mp_edge_out_kernel(float* __restrict__ out, int E, int C)
{
    int e = blockIdx.x * blockDim.x + threadIdx.x;
    if (e >= E) return;
    int r = g_row[e];
    int c = g_col[e];
    const float* a = g_pu + (size_t)r * PSTRIDE;
    const float* b = g_pm + (size_t)c * PSTRIDE;
    float* o = out + (size_t)e * C;
    if ((C & 1) == 0) {
        for (int k = 0; k < C; k += 2) {
            float2 av = *reinterpret_cast<const float2*>(a + k);
            float2 bv = *reinterpret_cast<const float2*>(b + k);
            float2 ov;
            ov.x = av.x + bv.x;
            ov.y = av.y + bv.y;
            *reinterpret_cast<float2*>(o + k) = ov;
        }
    } else {
        for (int k = 0; k < C; k++) o[k] = a[k] + b[k];
    }
}

// ---------------- host launch ----------------
extern "C" void kernel_launch(void* const* d_in, const int* in_sizes, int n_in,
                              void* d_out, int out_size)
{
    const float* x_user  = (const float*)d_in[0];
    const float* x_movie = (const float*)d_in[1];
    const void*  eidx    = d_in[2];
    const float* Wu = (const float*)d_in[3];
    const float* bu = (const float*)d_in[4];
    const float* Wm = (const float*)d_in[5];
    const float* bm = (const float*)d_in[6];
    const float* W1 = (const float*)d_in[7];
    const float* b1 = (const float*)d_in[8];
    const float* W2 = (const float*)d_in[9];
    const float* b2 = (const float*)d_in[10];
    const float* We = (const float*)d_in[11];
    const float* be = (const float*)d_in[12];
    float* out = (float*)d_out;

    const int H  = in_sizes[4];
    const int Fu = in_sizes[3] / H;
    const int Fm = in_sizes[5] / H;
    const int Nu = in_sizes[0] / Fu;
    const int Nm = in_sizes[1] / Fm;
    int E        = in_sizes[2] / 2;
    const int C  = in_sizes[12];
    const int Ntot = Nu + Nm;
    if (E > MAX_E) E = MAX_E;

    float* xp;  cudaGetSymbolAddress((void**)&xp,  g_x);
    float* hsp; cudaGetSymbolAddress((void**)&hsp, g_hs);

    const int nb = (Ntot + SCAN_B - 1) / SCAN_B;

    mp_detect_kernel<<<1, 32>>>(eidx);
    mp_deg_zero_kernel<<<(Ntot + 255) / 256, 256>>>(Ntot);
    mp_convert_kernel<<<(E + 255) / 256, 256>>>(eidx, E);
    mp_scan1_kernel<<<nb, SCAN_B>>>(Ntot);
    mp_scan2_kernel<<<1, MAX_SCAN_BLK>>>(nb);
    mp_scan3_kernel<<<(Ntot + 255) / 256, 256>>>(Ntot);
    mp_fill_kernel<<<(E + 255) / 256, 256>>>(E);

    // Input feature transforms into g_x
    {
        int g = (Nu + TILE_N - 1) / TILE_N;
        if (Fu == 32)       mp_linear_kernel< 32, false><<<g, 256>>>(x_user, Nu, Wu, bu, xp);
        else if (Fu == 64)  mp_linear_kernel< 64, false><<<g, 256>>>(x_user, Nu, Wu, bu, xp);
        else                mp_linear_kernel<128, false><<<g, 256>>>(x_user, Nu, Wu, bu, xp);
    }
    {
        int g = (Nm + TILE_N - 1) / TILE_N;
        float* dst = xp + (size_t)Nu * H_DIM;
        if (Fm == 32)       mp_linear_kernel< 32, false><<<g, 256>>>(x_movie, Nm, Wm, bm, dst);
        else if (Fm == 64)  mp_linear_kernel< 64, false><<<g, 256>>>(x_movie, Nm, Wm, bm, dst);
        else                mp_linear_kernel<128, false><<<g, 256>>>(x_movie, Nm, Wm, bm, dst);
    }

    int gN = (Ntot + TILE_N - 1) / TILE_N;
    int gA = (int)(((long long)Ntot * 32 + 255) / 256);

    // GNN layer 1
    mp_linear_kernel<128, true><<<gN, 256>>>(xp, Ntot, W1, b1, hsp);
    mp_aggregate_kernel<<<gA, 256>>>(Ntot);

    // GNN layer 2
    mp_linear_kernel<128, true><<<gN, 256>>>(xp, Ntot, W2, b2, hsp);
    mp_aggregate_kernel<<<gA, 256>>>(Ntot);

    // Edge head: project nodes to C dims, then gather+add per edge
    mp_proj_kernel<<<(Ntot + 255) / 256, 256>>>(We, be, Nu, Nm, C);
    mp_edge_out_kernel<<<(E + 255) / 256, 256>>>(out, E, C);
}